// round 6
// baseline (speedup 1.0000x reference)
#include <cuda_runtime.h>

#define NN 35
#define NE 1190
#define NB 148
typedef unsigned long long ull;

// ---------------- device globals ----------------
__device__ __align__(16) float g_h1[NN * 256];
__device__ __align__(16) float g_h2[NN * 256];
__device__ __align__(16) float g_h3[NN * 64];
__device__ __align__(16) float g_msg[NE * 256];
__device__ __align__(16) float g_m3[2][NE * 64];
__device__ __align__(16) float g_w2q[256 * 7 * 256];   // [i][v(6w+b)][o]
__device__ __align__(16) float g_w3q[256 * 7 * 64];
__device__ __align__(16) float g_l2t[256 * 256];
__device__ __align__(16) float g_l3t[256 * 64];
__device__ __align__(16) float g_ea8[NE * 8];
__device__ int   g_perm[NE];
__device__ int   g_offs[NN + 1];
__device__ float g_invd[NN];
__device__ unsigned g_barcnt = 0;
__device__ volatile unsigned g_barphase = 0;

// ---------------- f32x2 helpers ----------------
__device__ __forceinline__ ull fma2(ull a, ull b, ull c) {
    ull d; asm("fma.rn.f32x2 %0, %1, %2, %3;" : "=l"(d) : "l"(a), "l"(b), "l"(c));
    return d;
}
__device__ __forceinline__ ull relu2(ull t) {
    unsigned lo, hi;
    asm("mov.b64 {%0, %1}, %2;" : "=r"(lo), "=r"(hi) : "l"(t));
    float fl = fmaxf(__uint_as_float(lo), 0.f);
    float fh = fmaxf(__uint_as_float(hi), 0.f);
    ull r;
    asm("mov.b64 %0, {%1, %2};" : "=l"(r) : "r"(__float_as_uint(fl)), "r"(__float_as_uint(fh)));
    return r;
}
__device__ __forceinline__ float2 u2f(ull t) {
    unsigned lo, hi;
    asm("mov.b64 {%0, %1}, %2;" : "=r"(lo), "=r"(hi) : "l"(t));
    return make_float2(__uint_as_float(lo), __uint_as_float(hi));
}
__device__ __forceinline__ ull dup2(float v) {
    ull r; asm("mov.b64 %0, {%1, %1};" : "=l"(r) : "r"(__float_as_uint(v)));
    return r;
}

// ---------------- shared memory union ----------------
struct MsgSm {
    ull    xs[8 * 256];
    ull    ea[8 * 8];
    float2 red[32 * 9];
    int    src[8];
};
struct AggSm {
    int    perm[NE];
    int    off[NN + 1];
    float  inv[NN];
    float  hn[256];
    float2 sred[4][64];
};
union SmU { MsgSm m; AggSm a; char setup[8192]; };

// setup tile layout
#define B_L1   75
#define B_P2   (B_L1 + 256)
#define B_P3   (B_P2 + 16)
#define B_T2   (B_P3 + 64)
#define B_T3   (B_T2 + 16)
#define B_EA   (B_T3 + 5)
#define B_ALL  (B_EA + 1)

// ---------------- msg compute (one subtile: 8 edges x 64 o, i-range RS) ------
template <int NITB, int RS, int OTOT>
__device__ __forceinline__ void msg_tile(SmU* sm, const float* __restrict__ wq,
                                         float* __restrict__ msgout,
                                         int ibase, int oc, int e0) {
    constexpr int OP = OTOT / 2;
    int tid = threadIdx.x, lane = tid & 31, w = tid >> 5;
    int op = (oc >> 1) + lane;
    const ull* __restrict__ wq2 = (const ull*)wq;
    const ull* __restrict__ xs_u = sm->m.xs;
    const ull* __restrict__ ea_u = sm->m.ea;

    ull acc[8];
#pragma unroll
    for (int e = 0; e < 8; e++) acc[e] = 0ull;

#pragma unroll 1
    for (int itb = 0; itb < NITB; itb++) {
        int iloc = w * (NITB * 2) + itb * 2;
        int ig = ibase + iloc;
        ull w0[7], w1[7];
        size_t b0 = (size_t)(ig * 7) * OP + op;
        size_t b1 = (size_t)((ig + 1) * 7) * OP + op;
#pragma unroll
        for (int v = 0; v < 7; v++) { w0[v] = wq2[b0 + v * OP]; w1[v] = wq2[b1 + v * OP]; }
#pragma unroll
        for (int e = 0; e < 8; e++) {
            const ull* ap = ea_u + e * 8;
            ull a0 = ap[0], a1 = ap[1], a2 = ap[2], a3 = ap[3], a4 = ap[4], a5 = ap[5];
            ull x0 = xs_u[e * RS + iloc], x1 = xs_u[e * RS + iloc + 1];
            ull t0 = fma2(w0[0], a0, w0[6]);
            t0 = fma2(w0[1], a1, t0); t0 = fma2(w0[2], a2, t0);
            t0 = fma2(w0[3], a3, t0); t0 = fma2(w0[4], a4, t0);
            t0 = fma2(w0[5], a5, t0);
            acc[e] = fma2(x0, relu2(t0), acc[e]);
            ull t1 = fma2(w1[0], a0, w1[6]);
            t1 = fma2(w1[1], a1, t1); t1 = fma2(w1[2], a2, t1);
            t1 = fma2(w1[3], a3, t1); t1 = fma2(w1[4], a4, t1);
            t1 = fma2(w1[5], a5, t1);
            acc[e] = fma2(x1, relu2(t1), acc[e]);
        }
    }
    for (int p = 0; p < 8; p++) {
        if (w == p) {
            if (p == 0) {
#pragma unroll
                for (int e = 0; e < 8; e++) sm->m.red[lane * 9 + e] = u2f(acc[e]);
            } else {
#pragma unroll
                for (int e = 0; e < 8; e++) {
                    float2 f = u2f(acc[e]);
                    float2 r = sm->m.red[lane * 9 + e];
                    sm->m.red[lane * 9 + e] = make_float2(r.x + f.x, r.y + f.y);
                }
            }
        }
        __syncthreads();
    }
    for (int idx = tid; idx < 512; idx += 256) {
        int e = idx >> 6, oo = idx & 63, ee = e0 + e;
        if (ee < NE) {
            float2 pr = sm->m.red[(oo >> 1) * 9 + e];
            msgout[ee * OTOT + oc + oo] = (oo & 1) ? pr.y : pr.x;
        }
    }
}

template <int RS>
__device__ __forceinline__ void msg_load(SmU* sm, const int* __restrict__ eidx,
                                         const float* __restrict__ hin,
                                         int e0, int ibase) {
    int tid = threadIdx.x;
    if (tid < 8) {
        int ee = e0 + tid; if (ee >= NE) ee = NE - 1;
        sm->m.src[tid] = eidx[ee];
    }
    __syncthreads();
    if (tid < 64) {
        int e = tid >> 3, ee = e0 + e; if (ee >= NE) ee = NE - 1;
        sm->m.ea[tid] = dup2(g_ea8[ee * 8 + (tid & 7)]);
    }
    for (int idx = tid; idx < 8 * RS; idx += 256) {
        int e = idx / RS, c = ibase + (idx % RS);
        sm->m.xs[idx] = dup2(hin[sm->m.src[e] * 256 + c]);
    }
    __syncthreads();
}

__device__ __forceinline__ void load_csr(SmU* sm) {
    int tid = threadIdx.x;
    for (int j = tid; j < NE; j += 256) sm->a.perm[j] = g_perm[j];
    if (tid <= NN) sm->a.off[tid] = g_offs[tid];
    if (tid < NN) sm->a.inv[tid] = g_invd[tid];
    __syncthreads();
}

// ---------------- grid barrier (replay-safe, monotonic phase) ----------------
__device__ __forceinline__ void gridsync(unsigned target) {
    __threadfence();
    __syncthreads();
    if (threadIdx.x == 0) {
        unsigned nb = gridDim.x;
        unsigned old = atomicAdd(&g_barcnt, 1u);
        if (old == nb - 1) {
            atomicExch(&g_barcnt, 0u);
            __threadfence();
            g_barphase = target;
        } else {
            while ((int)(g_barphase - target) < 0) __nanosleep(64);
            __threadfence();
        }
    }
    __syncthreads();
}

// ---------------- the single persistent kernel ----------------
__global__ void __launch_bounds__(256, 2) k_all(
    const float* __restrict__ x,  const float* __restrict__ ea,
    const int* __restrict__ eidx,
    const float* __restrict__ n1w, const float* __restrict__ n1b,
    const float* __restrict__ l1w, const float* __restrict__ b1,
    const float* __restrict__ n2w, const float* __restrict__ n2b,
    const float* __restrict__ b2,
    const float* __restrict__ n3w, const float* __restrict__ n3b,
    const float* __restrict__ b3,
    const float* __restrict__ l2w, const float* __restrict__ l3w,
    float* __restrict__ out)
{
    __shared__ SmU sm;
    __shared__ unsigned s_base;
    int tid = threadIdx.x, bid = blockIdx.x;

    if (tid == 0) s_base = g_barphase;
    __syncthreads();
    unsigned base = s_base;

    // ================= phase 0: setup =================
    for (int b = bid; b < B_ALL; b += NB) {
        if (b < B_L1) {
            int e0 = b * 16, o = tid;
            float w[6];
#pragma unroll
            for (int v = 0; v < 6; v++) w[v] = n1w[o * 6 + v];
            float bb = n1b[o];
#pragma unroll
            for (int k = 0; k < 16; k++) {
                int e = e0 + k;
                if (e < NE) {
                    float t = bb;
#pragma unroll
                    for (int v = 0; v < 6; v++) t = fmaf(w[v], ea[e * 6 + v], t);
                    g_msg[e * 256 + o] = x[eidx[e]] * fmaxf(t, 0.f);
                }
            }
        } else if (b < B_P2) {
            int i = b - B_L1, o = tid, io = i * 256 + o;
#pragma unroll
            for (int v = 0; v < 6; v++) g_w2q[(i * 7 + v) * 256 + o] = n2w[io * 6 + v];
            g_w2q[(i * 7 + 6) * 256 + o] = n2b[io];
        } else if (b < B_P3) {
            int rb = b - B_P2;
#pragma unroll
            for (int r = 0; r < 4; r++) {
                int i = rb * 16 + r * 4 + (tid >> 6), o = tid & 63, io = i * 64 + o;
#pragma unroll
                for (int v = 0; v < 6; v++) g_w3q[(i * 7 + v) * 64 + o] = n3w[io * 6 + v];
                g_w3q[(i * 7 + 6) * 64 + o] = n3b[io];
            }
        } else if (b < B_T2) {
            float* tile = (float*)sm.setup;
            int rb = b - B_P3, bo = (rb & 7) * 32, bi = (rb >> 3) * 32;
            int tx = tid & 31, ty = tid >> 5;
#pragma unroll
            for (int r = 0; r < 4; r++)
                tile[(ty + r * 8) * 33 + tx] = l2w[(bo + ty + r * 8) * 256 + bi + tx];
            __syncthreads();
#pragma unroll
            for (int r = 0; r < 4; r++)
                g_l2t[(bi + ty + r * 8) * 256 + bo + tx] = tile[tx * 33 + ty + r * 8];
        } else if (b < B_T3) {
            float* tile = (float*)sm.setup;
            int rb = b - B_T2, bo = (rb & 1) * 32, bi = (rb >> 1) * 32;
            int tx = tid & 31, ty = tid >> 5;
#pragma unroll
            for (int r = 0; r < 4; r++)
                tile[(ty + r * 8) * 33 + tx] = l3w[(bo + ty + r * 8) * 256 + bi + tx];
            __syncthreads();
#pragma unroll
            for (int r = 0; r < 4; r++)
                g_l3t[(bi + ty + r * 8) * 64 + bo + tx] = tile[tx * 33 + ty + r * 8];
        } else if (b < B_EA) {
            int rb = b - B_T3;
            for (int idx = rb * 256 + tid; idx < NE * 8; idx += 5 * 256) {
                int e = idx >> 3, v = idx & 7;
                g_ea8[idx] = (v < 6) ? ea[e * 6 + v] : 0.f;
            }
        } else {
            int* s_dst = (int*)sm.setup;
            int* s_cnt = s_dst + NE;
            int* s_off = s_cnt + 7 * NN;
            for (int e = tid; e < NE; e += 256) s_dst[e] = eidx[NE + e];
            __syncthreads();
            if (tid < 7 * NN) {
                int c = tid / NN, n = tid % NN;
                int lo = c * 170, cnt = 0;
                for (int e = lo; e < lo + 170; e++) cnt += (s_dst[e] == n);
                s_cnt[c * NN + n] = cnt;
            }
            __syncthreads();
            if (tid == 0) {
                int off = 0;
                for (int n = 0; n < NN; n++) {
                    s_off[n] = off;
                    for (int c = 0; c < 7; c++) {
                        int t = s_cnt[c * NN + n];
                        s_cnt[c * NN + n] = off;
                        off += t;
                    }
                }
                s_off[NN] = off;
            }
            __syncthreads();
            if (tid < 7 * NN) {
                int c = tid / NN, n = tid % NN;
                int lo = c * 170, p = s_cnt[c * NN + n];
                for (int e = lo; e < lo + 170; e++)
                    if (s_dst[e] == n) g_perm[p++] = e;
            }
            if (tid <= NN) g_offs[tid] = s_off[tid];
            if (tid < NN) g_invd[tid] = 1.0f / (float)max(s_off[tid + 1] - s_off[tid], 1);
        }
        __syncthreads();
    }
    gridsync(base + 1);

    // ================= phase 1: agg1 =================
    load_csr(&sm);
    for (int t = bid; t < NN * 4; t += NB) {
        int n = t % NN, oc = (t / NN) * 64;
        int o64 = tid & 63, g = tid >> 6, o = oc + o64;
        int j0 = sm.a.off[n], j1 = sm.a.off[n + 1];
        float acc = 0.f;
        for (int j = j0 + g; j < j1; j += 4) acc += g_msg[sm.a.perm[j] * 256 + o];
        sm.a.sred[g][o64] = make_float2(acc, 0.f);
        __syncthreads();
        if (tid < 64) {
            int oo = oc + tid;
            float tot = sm.a.sred[0][tid].x + sm.a.sred[1][tid].x +
                        sm.a.sred[2][tid].x + sm.a.sred[3][tid].x;
            g_h1[n * 256 + oo] =
                fmaxf(fmaf(tot, sm.a.inv[n], fmaf(x[n], l1w[oo], b1[oo])), 0.f);
        }
        __syncthreads();
    }
    gridsync(base + 2);

    // ================= phase 2: msg2 =================
    for (int st = bid; st < 149 * 4; st += NB) {
        int et = st % 149, oc = (st / 149) * 64;
        msg_load<256>(&sm, eidx, g_h1, et * 8, 0);
        msg_tile<16, 256, 256>(&sm, g_w2q, g_msg, 0, oc, et * 8);
        __syncthreads();
    }
    gridsync(base + 3);

    // ================= phase 3: agg2 =================
    load_csr(&sm);
    for (int t = bid; t < NN * 4; t += NB) {
        int n = t % NN, oc = (t / NN) * 64;
        int o64 = tid & 63, g = tid >> 6, o = oc + o64;
        sm.a.hn[tid] = g_h1[n * 256 + tid];
        __syncthreads();
        int j0 = sm.a.off[n], j1 = sm.a.off[n + 1];
        float macc = 0.f;
        for (int j = j0 + g; j < j1; j += 4) macc += g_msg[sm.a.perm[j] * 256 + o];
        float lin = 0.f;
        int ib = g * 64;
#pragma unroll 8
        for (int i = 0; i < 64; i++) lin = fmaf(sm.a.hn[ib + i], g_l2t[(ib + i) * 256 + o], lin);
        sm.a.sred[g][o64] = make_float2(macc, lin);
        __syncthreads();
        if (tid < 64) {
            float2 r0 = sm.a.sred[0][tid], r1 = sm.a.sred[1][tid];
            float2 r2 = sm.a.sred[2][tid], r3 = sm.a.sred[3][tid];
            float m = (r0.x + r1.x) + (r2.x + r3.x);
            float l = (r0.y + r1.y) + (r2.y + r3.y);
            int oo = oc + tid;
            g_h2[n * 256 + oo] = fmaxf(fmaf(m, sm.a.inv[n], l + b2[oo]), 0.f);
        }
        __syncthreads();
    }
    gridsync(base + 4);

    // ================= phase 4: msg3 =================
    for (int st = bid; st < 149 * 2; st += NB) {
        int et = st % 149, ih = st / 149;
        msg_load<128>(&sm, eidx, g_h2, et * 8, ih * 128);
        msg_tile<8, 128, 64>(&sm, g_w3q, &g_m3[ih][0], ih * 128, 0, et * 8);
        __syncthreads();
    }
    gridsync(base + 5);

    // ================= phase 5: agg3 =================
    load_csr(&sm);
    for (int t = bid; t < NN; t += NB) {
        int n = t;
        int o64 = tid & 63, g = tid >> 6, o = o64;
        sm.a.hn[tid] = g_h2[n * 256 + tid];
        __syncthreads();
        int j0 = sm.a.off[n], j1 = sm.a.off[n + 1];
        float macc = 0.f;
        for (int j = j0 + g; j < j1; j += 4) {
            int e = sm.a.perm[j];
            macc += g_m3[0][e * 64 + o] + g_m3[1][e * 64 + o];
        }
        float lin = 0.f;
        int ib = g * 64;
#pragma unroll 8
        for (int i = 0; i < 64; i++) lin = fmaf(sm.a.hn[ib + i], g_l3t[(ib + i) * 64 + o], lin);
        sm.a.sred[g][o64] = make_float2(macc, lin);
        __syncthreads();
        if (tid < 64) {
            float2 r0 = sm.a.sred[0][tid], r1 = sm.a.sred[1][tid];
            float2 r2 = sm.a.sred[2][tid], r3 = sm.a.sred[3][tid];
            float m = (r0.x + r1.x) + (r2.x + r3.x);
            float l = (r0.y + r1.y) + (r2.y + r3.y);
            g_h3[n * 64 + tid] = fmaxf(fmaf(m, sm.a.inv[n], l + b3[tid]), 0.f);
        }
        __syncthreads();
    }
    gridsync(base + 6);

    // ================= phase 6: CBT =================
    {
        int w = tid >> 5, lane = tid & 31;
        for (int p = bid * 8 + w; p < NN * NN; p += NB * 8) {
            int a = p / NN, bb = p % NN;
            float d = fabsf(g_h3[a * 64 + lane] - g_h3[bb * 64 + lane]) +
                      fabsf(g_h3[a * 64 + lane + 32] - g_h3[bb * 64 + lane + 32]);
#pragma unroll
            for (int s = 16; s; s >>= 1) d += __shfl_xor_sync(0xffffffffu, d, s);
            if (lane == 0) out[p] = d;
        }
    }
}

// ---------------- launch ----------------
extern "C" void kernel_launch(void* const* d_in, const int* in_sizes, int n_in,
                              void* d_out, int out_size) {
    const float* x   = (const float*)d_in[0];
    const float* ea  = (const float*)d_in[1];
    const int*   ei  = (const int*)d_in[2];
    const float* n1w = (const float*)d_in[3];
    const float* n1b = (const float*)d_in[4];
    const float* l1w = (const float*)d_in[5];
    const float* b1  = (const float*)d_in[6];
    const float* n2w = (const float*)d_in[7];
    const float* n2b = (const float*)d_in[8];
    const float* l2w = (const float*)d_in[9];
    const float* b2  = (const float*)d_in[10];
    const float* n3w = (const float*)d_in[11];
    const float* n3b = (const float*)d_in[12];
    const float* l3w = (const float*)d_in[13];
    const float* b3  = (const float*)d_in[14];
    float* out = (float*)d_out;
    (void)in_sizes; (void)n_in; (void)out_size;

    k_all<<<NB, 256>>>(x, ea, ei, n1w, n1b, l1w, b1,
                       n2w, n2b, b2, n3w, n3b, b3, l2w, l3w, out);
}

// round 7
// speedup vs baseline: 1.3884x; 1.3884x over previous
#include <cuda_runtime.h>

#define NN 35
#define NE 1190
typedef unsigned long long ull;

// ---------------- scratch ----------------
__device__ __align__(16) float g_h1[NN * 256];
__device__ __align__(16) float g_h2[NN * 256];
__device__ __align__(16) float g_h3[NN * 64];
__device__ __align__(16) float g_msg[NE * 256];
__device__ __align__(16) float g_m3[2][NE * 64];
__device__ __align__(16) float g_w2q[256 * 7 * 256];   // [i][v(6w+b)][o]
__device__ __align__(16) float g_w3q[256 * 7 * 64];
__device__ __align__(16) float g_l2t[256 * 256];
__device__ __align__(16) float g_l3t[256 * 64];
__device__ __align__(16) float g_ea8[NE * 8];
__device__ int   g_perm[NE];
__device__ int   g_offs[NN + 1];
__device__ float g_invd[NN];

// ---------------- f32x2 helpers ----------------
__device__ __forceinline__ ull fma2(ull a, ull b, ull c) {
    ull d; asm("fma.rn.f32x2 %0, %1, %2, %3;" : "=l"(d) : "l"(a), "l"(b), "l"(c));
    return d;
}
__device__ __forceinline__ ull relu2(ull t) {
    unsigned lo, hi;
    asm("mov.b64 {%0, %1}, %2;" : "=r"(lo), "=r"(hi) : "l"(t));
    float fl = fmaxf(__uint_as_float(lo), 0.f);
    float fh = fmaxf(__uint_as_float(hi), 0.f);
    ull r;
    asm("mov.b64 %0, {%1, %2};" : "=l"(r) : "r"(__float_as_uint(fl)), "r"(__float_as_uint(fh)));
    return r;
}
__device__ __forceinline__ float2 u2f(ull t) {
    unsigned lo, hi;
    asm("mov.b64 {%0, %1}, %2;" : "=r"(lo), "=r"(hi) : "l"(t));
    return make_float2(__uint_as_float(lo), __uint_as_float(hi));
}
__device__ __forceinline__ ull dup2(float v) {
    ull r; asm("mov.b64 %0, {%1, %1};" : "=l"(r) : "r"(__float_as_uint(v)));
    return r;
}

// ---------------- fused setup ----------------
#define B_L1   75
#define B_P2   (B_L1 + 256)
#define B_P3   (B_P2 + 16)
#define B_T2   (B_P3 + 64)
#define B_T3   (B_T2 + 16)
#define B_EA   (B_T3 + 5)
#define B_ALL  (B_EA + 1)

__global__ void __launch_bounds__(256) k_setup(
    const float* __restrict__ x,  const float* __restrict__ ea,
    const int* __restrict__ eidx,
    const float* __restrict__ n1w, const float* __restrict__ n1b,
    const float* __restrict__ n2w, const float* __restrict__ n2b,
    const float* __restrict__ n3w, const float* __restrict__ n3b,
    const float* __restrict__ l2w, const float* __restrict__ l3w)
{
    __shared__ __align__(16) char smbuf[8192];
    int b = blockIdx.x, tid = threadIdx.x;

    if (b < B_L1) {                                      // layer-1 messages (c_in=1)
        int e0 = b * 16, o = tid;
        float w[6];
#pragma unroll
        for (int v = 0; v < 6; v++) w[v] = n1w[o * 6 + v];
        float bb = n1b[o];
#pragma unroll
        for (int k = 0; k < 16; k++) {
            int e = e0 + k;
            if (e < NE) {
                float t = bb;
#pragma unroll
                for (int v = 0; v < 6; v++) t = fmaf(w[v], ea[e * 6 + v], t);
                g_msg[e * 256 + o] = x[eidx[e]] * fmaxf(t, 0.f);
            }
        }
    } else if (b < B_P2) {                               // pack nn2
        int i = b - B_L1, o = tid, io = i * 256 + o;
#pragma unroll
        for (int v = 0; v < 6; v++) g_w2q[(i * 7 + v) * 256 + o] = n2w[io * 6 + v];
        g_w2q[(i * 7 + 6) * 256 + o] = n2b[io];
    } else if (b < B_P3) {                               // pack nn3
        int rb = b - B_P2;
#pragma unroll
        for (int r = 0; r < 4; r++) {
            int i = rb * 16 + r * 4 + (tid >> 6), o = tid & 63, io = i * 64 + o;
#pragma unroll
            for (int v = 0; v < 6; v++) g_w3q[(i * 7 + v) * 64 + o] = n3w[io * 6 + v];
            g_w3q[(i * 7 + 6) * 64 + o] = n3b[io];
        }
    } else if (b < B_T2) {                               // transpose lin2
        float* tile = (float*)smbuf;
        int rb = b - B_P3, bo = (rb & 7) * 32, bi = (rb >> 3) * 32;
        int tx = tid & 31, ty = tid >> 5;
#pragma unroll
        for (int r = 0; r < 4; r++)
            tile[(ty + r * 8) * 33 + tx] = l2w[(bo + ty + r * 8) * 256 + bi + tx];
        __syncthreads();
#pragma unroll
        for (int r = 0; r < 4; r++)
            g_l2t[(bi + ty + r * 8) * 256 + bo + tx] = tile[tx * 33 + ty + r * 8];
    } else if (b < B_T3) {                               // transpose lin3
        float* tile = (float*)smbuf;
        int rb = b - B_T2, bo = (rb & 1) * 32, bi = (rb >> 1) * 32;
        int tx = tid & 31, ty = tid >> 5;
#pragma unroll
        for (int r = 0; r < 4; r++)
            tile[(ty + r * 8) * 33 + tx] = l3w[(bo + ty + r * 8) * 256 + bi + tx];
        __syncthreads();
#pragma unroll
        for (int r = 0; r < 4; r++)
            g_l3t[(bi + ty + r * 8) * 64 + bo + tx] = tile[tx * 33 + ty + r * 8];
    } else if (b < B_EA) {                               // pad edge attrs
        int rb = b - B_T3;
        for (int idx = rb * 256 + tid; idx < NE * 8; idx += 5 * 256) {
            int e = idx >> 3, v = idx & 7;
            g_ea8[idx] = (v < 6) ? ea[e * 6 + v] : 0.f;
        }
    } else {                                             // deterministic CSR by dst
        int* s_dst = (int*)smbuf;
        int* s_cnt = s_dst + NE;
        int* s_off = s_cnt + 7 * NN;
        for (int e = tid; e < NE; e += 256) s_dst[e] = eidx[NE + e];
        __syncthreads();
        if (tid < 7 * NN) {
            int c = tid / NN, n = tid % NN;
            int lo = c * 170, cnt = 0;
            for (int e = lo; e < lo + 170; e++) cnt += (s_dst[e] == n);
            s_cnt[c * NN + n] = cnt;
        }
        __syncthreads();
        if (tid == 0) {
            int off = 0;
            for (int n = 0; n < NN; n++) {
                s_off[n] = off;
                for (int c = 0; c < 7; c++) {
                    int t = s_cnt[c * NN + n];
                    s_cnt[c * NN + n] = off;
                    off += t;
                }
            }
            s_off[NN] = off;
        }
        __syncthreads();
        if (tid < 7 * NN) {
            int c = tid / NN, n = tid % NN;
            int lo = c * 170, p = s_cnt[c * NN + n];
            for (int e = lo; e < lo + 170; e++)
                if (s_dst[e] == n) g_perm[p++] = e;
        }
        if (tid <= NN) g_offs[tid] = s_off[tid];
        if (tid < NN) g_invd[tid] = 1.0f / (float)max(s_off[tid + 1] - s_off[tid], 1);
    }
}

// ---------------- batched gather helper (MLP-friendly) ----------------
__device__ __forceinline__ float gather16(const float* __restrict__ base, int stride,
                                          int o, int j0, int j1, int g) {
    float acc = 0.f;
#pragma unroll
    for (int k = 0; k < 16; k++) {
        int j = j0 + g + 4 * k;
        if (j < j1) acc += base[g_perm[j] * stride + o];
    }
    for (int j = j0 + g + 64; j < j1; j += 4) acc += base[g_perm[j] * stride + o];
    return acc;
}

// ---------------- layer-1 aggregate ----------------
__global__ void __launch_bounds__(256) k_agg1(const float* __restrict__ x,
                                              const float* __restrict__ lw,
                                              const float* __restrict__ b) {
    __shared__ float sred[4][64];
    int n = blockIdx.x, o = blockIdx.y * 64 + (threadIdx.x & 63), g = threadIdx.x >> 6;
    int j0 = g_offs[n], j1 = g_offs[n + 1];
    float acc = gather16(g_msg, 256, o, j0, j1, g);
    sred[g][threadIdx.x & 63] = acc;
    __syncthreads();
    if (threadIdx.x < 64) {
        int oo = blockIdx.y * 64 + threadIdx.x;
        float tot = sred[0][threadIdx.x] + sred[1][threadIdx.x] +
                    sred[2][threadIdx.x] + sred[3][threadIdx.x];
        g_h1[n * 256 + oo] = fmaxf(fmaf(tot, g_invd[n], fmaf(x[n], lw[oo], b[oo])), 0.f);
    }
}

// ---------------- heavy message kernel ----------------
// 256 thr = 8 warps; i split 8 ways; lane owns o-pair; ET=16 edges per tile.
// L=2: grid (75,4): blockIdx.y = 64-o chunk, i-range 256 (32 i per warp).
// L=3: grid (75,2): blockIdx.y = i-half, o-range 64 (16 i per warp).
#define ET 16
struct MsgSm {
    union {
        ull    xs[ET * 256];                 // duplicated source features
        float2 red[8 * 32 * (ET + 1)];       // aliased after compute
    };
    ull ea[ET * 8];                          // duplicated edge attrs (pairs 16B-aligned)
    int src[ET];
};

template <int L>
__global__ void __launch_bounds__(256, 2) k_msg(const int* __restrict__ eidx) {
    constexpr int OTOT = (L == 3) ? 64 : 256;
    constexpr int OP = OTOT / 2;
    constexpr int IW = (L == 3) ? 128 : 256;
    constexpr int NITB = IW / 16;            // itb count per warp (2 i's each)
    const float* __restrict__ wq  = (L == 3) ? g_w3q : g_w2q;
    const float* __restrict__ hin = (L == 3) ? g_h2 : g_h1;

    __shared__ MsgSm sm;
    int tid = threadIdx.x, lane = tid & 31, w = tid >> 5;
    int e0 = blockIdx.x * ET;
    int oc = (L == 3) ? 0 : blockIdx.y * 64;
    int ih = (L == 3) ? blockIdx.y : 0;
    int op = (oc >> 1) + lane;
    float* __restrict__ msgout = (L == 3) ? &g_m3[ih][0] : g_msg;

    // ---- load tile inputs ----
    if (tid < ET) {
        int ee = e0 + tid; if (ee >= NE) ee = NE - 1;
        sm.src[tid] = eidx[ee];
    }
    __syncthreads();
    if (tid < ET * 8) {
        int e = tid >> 3, ee = e0 + e; if (ee >= NE) ee = NE - 1;
        sm.ea[tid] = dup2(g_ea8[ee * 8 + (tid & 7)]);
    }
    for (int idx = tid; idx < ET * IW; idx += 256) {
        int e = idx / IW, c = ih * 128 + (idx % IW);
        sm.xs[idx] = dup2(hin[sm.src[e] * 256 + c]);
    }
    __syncthreads();

    const ull* __restrict__ wq2 = (const ull*)wq;
    const ulonglong2* __restrict__ xs2 = (const ulonglong2*)sm.xs;
    const ulonglong2* __restrict__ ea2 = (const ulonglong2*)sm.ea;

    ull acc[ET];
#pragma unroll
    for (int e = 0; e < ET; e++) acc[e] = 0ull;

    ull wA[14], wB[14];
    const int i0 = ih * 128 + w * (NITB * 2);            // this warp's first global i

    // prefetch itb 0
    {
        size_t b0 = (size_t)(i0 * 7) * OP + op;
#pragma unroll
        for (int v = 0; v < 7; v++) { wA[v] = wq2[b0 + v * OP]; wA[7 + v] = wq2[b0 + 7 * OP + v * OP]; }
    }

#pragma unroll 1
    for (int itb = 0; itb < NITB; itb += 2) {
        // prefetch itb+1 into wB
        {
            size_t b0 = (size_t)((i0 + (itb + 1) * 2) * 7) * OP + op;
#pragma unroll
            for (int v = 0; v < 7; v++) { wB[v] = wq2[b0 + v * OP]; wB[7 + v] = wq2[b0 + 7 * OP + v * OP]; }
        }
        // compute itb with wA
        {
            int iloc = w * (NITB * 2) + itb * 2;
#pragma unroll
            for (int e = 0; e < ET; e++) {
                ulonglong2 A01 = ea2[e * 4 + 0], A23 = ea2[e * 4 + 1], A45 = ea2[e * 4 + 2];
                ulonglong2 X = xs2[(e * IW + iloc) >> 1];
                ull t0 = fma2(wA[0], A01.x, wA[6]);
                t0 = fma2(wA[1], A01.y, t0); t0 = fma2(wA[2], A23.x, t0);
                t0 = fma2(wA[3], A23.y, t0); t0 = fma2(wA[4], A45.x, t0);
                t0 = fma2(wA[5], A45.y, t0);
                acc[e] = fma2(X.x, relu2(t0), acc[e]);
                ull t1 = fma2(wA[7], A01.x, wA[13]);
                t1 = fma2(wA[8], A01.y, t1); t1 = fma2(wA[9], A23.x, t1);
                t1 = fma2(wA[10], A23.y, t1); t1 = fma2(wA[11], A45.x, t1);
                t1 = fma2(wA[12], A45.y, t1);
                acc[e] = fma2(X.y, relu2(t1), acc[e]);
            }
        }
        // prefetch itb+2 into wA
        if (itb + 2 < NITB) {
            size_t b0 = (size_t)((i0 + (itb + 2) * 2) * 7) * OP + op;
#pragma unroll
            for (int v = 0; v < 7; v++) { wA[v] = wq2[b0 + v * OP]; wA[7 + v] = wq2[b0 + 7 * OP + v * OP]; }
        }
        // compute itb+1 with wB
        {
            int iloc = w * (NITB * 2) + (itb + 1) * 2;
#pragma unroll
            for (int e = 0; e < ET; e++) {
                ulonglong2 A01 = ea2[e * 4 + 0], A23 = ea2[e * 4 + 1], A45 = ea2[e * 4 + 2];
                ulonglong2 X = xs2[(e * IW + iloc) >> 1];
                ull t0 = fma2(wB[0], A01.x, wB[6]);
                t0 = fma2(wB[1], A01.y, t0); t0 = fma2(wB[2], A23.x, t0);
                t0 = fma2(wB[3], A23.y, t0); t0 = fma2(wB[4], A45.x, t0);
                t0 = fma2(wB[5], A45.y, t0);
                acc[e] = fma2(X.x, relu2(t0), acc[e]);
                ull t1 = fma2(wB[7], A01.x, wB[13]);
                t1 = fma2(wB[8], A01.y, t1); t1 = fma2(wB[9], A23.x, t1);
                t1 = fma2(wB[10], A23.y, t1); t1 = fma2(wB[11], A45.x, t1);
                t1 = fma2(wB[12], A45.y, t1);
                acc[e] = fma2(X.y, relu2(t1), acc[e]);
            }
        }
    }

    // ---- single-pass reduction (red aliases xs; all xs reads are done) ----
    __syncthreads();
#pragma unroll
    for (int e = 0; e < ET; e++) sm.red[(w * 32 + lane) * (ET + 1) + e] = u2f(acc[e]);
    __syncthreads();
#pragma unroll
    for (int half = 0; half < 2; half++) {
        int idx = half * 256 + tid;                      // 512 (opair, e) outputs
        int opair = idx & 31, e = idx >> 5;
        int ee = e0 + e;
        if (ee < NE) {
            float2 s = make_float2(0.f, 0.f);
#pragma unroll
            for (int ww = 0; ww < 8; ww++) {
                float2 p = sm.red[(ww * 32 + opair) * (ET + 1) + e];
                s.x += p.x; s.y += p.y;
            }
            *(float2*)(msgout + ee * OTOT + oc + 2 * opair) = s;
        }
    }
}

// ---------------- layers 2/3 aggregate + root linear + relu ----------------
template <int L>
__global__ void __launch_bounds__(256) k_aggf(const float* __restrict__ b) {
    constexpr int OTOT = (L == 3) ? 64 : 256;
    const float* __restrict__ hin = (L == 3) ? g_h2 : g_h1;
    const float* __restrict__ lt  = (L == 3) ? g_l3t : g_l2t;
    float* __restrict__ hout      = (L == 3) ? g_h3 : g_h2;

    __shared__ float hn[256];
    __shared__ float2 sred[4][64];
    int n = blockIdx.x, o64 = threadIdx.x & 63, g = threadIdx.x >> 6;
    int oc = blockIdx.y * 64, o = oc + o64;

    hn[threadIdx.x] = hin[n * 256 + threadIdx.x];
    __syncthreads();

    int j0 = g_offs[n], j1 = g_offs[n + 1];
    float macc;
    if (L == 3) {
        macc = 0.f;
#pragma unroll
        for (int k = 0; k < 16; k++) {
            int j = j0 + g + 4 * k;
            if (j < j1) {
                int e = g_perm[j];
                macc += g_m3[0][e * 64 + o] + g_m3[1][e * 64 + o];
            }
        }
        for (int j = j0 + g + 64; j < j1; j += 4) {
            int e = g_perm[j];
            macc += g_m3[0][e * 64 + o] + g_m3[1][e * 64 + o];
        }
    } else {
        macc = gather16(g_msg, OTOT, o, j0, j1, g);
    }

    float lin = 0.f;
    int ib = g * 64;
#pragma unroll
    for (int i = 0; i < 64; i++) lin = fmaf(hn[ib + i], lt[(ib + i) * OTOT + o], lin);

    sred[g][o64] = make_float2(macc, lin);
    __syncthreads();
    if (threadIdx.x < 64) {
        float2 r0 = sred[0][threadIdx.x], r1 = sred[1][threadIdx.x];
        float2 r2 = sred[2][threadIdx.x], r3 = sred[3][threadIdx.x];
        float m = (r0.x + r1.x) + (r2.x + r3.x);
        float l = (r0.y + r1.y) + (r2.y + r3.y);
        int oo = oc + threadIdx.x;
        hout[n * OTOT + oo] = fmaxf(fmaf(m, g_invd[n], l + b[oo]), 0.f);
    }
}

// ---------------- CBT ----------------
__global__ void k_cbt(float* __restrict__ out) {
    int p = blockIdx.x, a = p / NN, bb = p % NN, c = threadIdx.x;
    float d = fabsf(g_h3[a * 64 + c] - g_h3[bb * 64 + c]) +
              fabsf(g_h3[a * 64 + c + 32] - g_h3[bb * 64 + c + 32]);
#pragma unroll
    for (int s = 16; s; s >>= 1) d += __shfl_xor_sync(0xffffffffu, d, s);
    if (c == 0) out[p] = d;
}

// ---------------- launch ----------------
extern "C" void kernel_launch(void* const* d_in, const int* in_sizes, int n_in,
                              void* d_out, int out_size) {
    const float* x   = (const float*)d_in[0];
    const float* ea  = (const float*)d_in[1];
    const int*   ei  = (const int*)d_in[2];
    const float* n1w = (const float*)d_in[3];
    const float* n1b = (const float*)d_in[4];
    const float* l1w = (const float*)d_in[5];
    const float* b1  = (const float*)d_in[6];
    const float* n2w = (const float*)d_in[7];
    const float* n2b = (const float*)d_in[8];
    const float* l2w = (const float*)d_in[9];
    const float* b2  = (const float*)d_in[10];
    const float* n3w = (const float*)d_in[11];
    const float* n3b = (const float*)d_in[12];
    const float* l3w = (const float*)d_in[13];
    const float* b3  = (const float*)d_in[14];
    float* out = (float*)d_out;
    (void)in_sizes; (void)n_in; (void)out_size;

    k_setup<<<B_ALL, 256>>>(x, ea, ei, n1w, n1b, n2w, n2b, n3w, n3b, l2w, l3w);
    k_agg1<<<dim3(NN, 4), 256>>>(x, l1w, b1);
    k_msg<2><<<dim3((NE + ET - 1) / ET, 4), 256>>>(ei);
    k_aggf<2><<<dim3(NN, 4), 256>>>(b2);
    k_msg<3><<<dim3((NE + ET - 1) / ET, 2), 256>>>(ei);
    k_aggf<3><<<dim3(NN, 1), 256>>>(b3);
    k_cbt<<<NN * NN, 32>>>(out);
}